// round 2
// baseline (speedup 1.0000x reference)
#include <cuda_runtime.h>
#include <math.h>
#include <float.h>

#define B_   2
#define NPTS 2048
#define C_   256
#define KNB  32
#define HID  512
#define CPH  32
#define M1   (B_*NPTS)        // 4096
#define M2   (B_*NPTS*KNB)    // 131072
#define EPSB 1e-5f

// ---------------- device scratch (static allocation, allowed) ----------------
__device__ float g_q[M1*C_];
__device__ float g_k[M1*C_];
__device__ float g_v[M1*C_];
__device__ float g_tmp[M1*HID];
__device__ float g_sq[M1];
__device__ float g_dist[(size_t)B_*NPTS*NPTS];
__device__ int   g_idx[M2];
__device__ float g_big0[(size_t)M2*C_];   // masked_pos, then reused as vecin
__device__ float g_big1[(size_t)M2*C_];   // posb raw
__device__ float g_big2[(size_t)M2*C_];   // value
__device__ float g_s1[(size_t)M2*CPH];
__device__ float g_s2[(size_t)M2*CPH];
__device__ float g_xattn[M1*C_];
__device__ float g_h[M1*HID];
__device__ double g_dsum[HID];
__device__ double g_dsum2[HID];
__device__ float g_mean[HID];
__device__ float g_var[HID];

// ---------------- generic GEMM: C[m,n] = sum_k A[m,k]*W[n,k] ----------------
__global__ __launch_bounds__(256)
void gemm_tn_kernel(const float* __restrict__ A, const float* __restrict__ W,
                    float* __restrict__ C, int M, int N, int K)
{
    __shared__ float As[16][64];
    __shared__ float Bs[16][64];
    int tid = threadIdx.x;
    int tx = tid & 15, ty = tid >> 4;
    int m0 = blockIdx.y * 64, n0 = blockIdx.x * 64;
    float acc[4][4] = {};

    for (int k0 = 0; k0 < K; k0 += 16) {
        #pragma unroll
        for (int i = 0; i < 4; i++) {
            int e = tid + i * 256;
            int r = e >> 4, c = e & 15;
            int gm = m0 + r, gk = k0 + c;
            As[c][r] = (gm < M && gk < K) ? A[(size_t)gm * K + gk] : 0.f;
            int gn = n0 + r;
            Bs[c][r] = (gn < N && gk < K) ? W[(size_t)gn * K + gk] : 0.f;
        }
        __syncthreads();
        #pragma unroll
        for (int kk = 0; kk < 16; kk++) {
            float a[4], b[4];
            #pragma unroll
            for (int i = 0; i < 4; i++) a[i] = As[kk][ty * 4 + i];
            #pragma unroll
            for (int j = 0; j < 4; j++) b[j] = Bs[kk][tx * 4 + j];
            #pragma unroll
            for (int i = 0; i < 4; i++)
                #pragma unroll
                for (int j = 0; j < 4; j++)
                    acc[i][j] += a[i] * b[j];
        }
        __syncthreads();
    }
    #pragma unroll
    for (int i = 0; i < 4; i++) {
        int gm = m0 + ty * 4 + i;
        if (gm >= M) continue;
        #pragma unroll
        for (int j = 0; j < 4; j++) {
            int gn = n0 + tx * 4 + j;
            if (gn < N) C[(size_t)gm * N + gn] = acc[i][j];
        }
    }
}

// ---------------- dist = sq[n] + sq[m] - 2*key_n.key_m  (per batch) ----------------
__global__ __launch_bounds__(256)
void dist_kernel(const float* __restrict__ key, const float* __restrict__ sq,
                 float* __restrict__ dist)
{
    int b = blockIdx.z;
    const float* A  = key + (size_t)b * NPTS * C_;
    const float* sb = sq + b * NPTS;
    float* D = dist + (size_t)b * NPTS * NPTS;

    __shared__ float As[16][64];
    __shared__ float Bs[16][64];
    int tid = threadIdx.x;
    int tx = tid & 15, ty = tid >> 4;
    int m0 = blockIdx.y * 64, n0 = blockIdx.x * 64;
    float acc[4][4] = {};

    for (int k0 = 0; k0 < C_; k0 += 16) {
        #pragma unroll
        for (int i = 0; i < 4; i++) {
            int e = tid + i * 256;
            int r = e >> 4, c = e & 15;
            As[c][r] = A[(size_t)(m0 + r) * C_ + k0 + c];
            Bs[c][r] = A[(size_t)(n0 + r) * C_ + k0 + c];
        }
        __syncthreads();
        #pragma unroll
        for (int kk = 0; kk < 16; kk++) {
            float a[4], bb[4];
            #pragma unroll
            for (int i = 0; i < 4; i++) a[i] = As[kk][ty * 4 + i];
            #pragma unroll
            for (int j = 0; j < 4; j++) bb[j] = Bs[kk][tx * 4 + j];
            #pragma unroll
            for (int i = 0; i < 4; i++)
                #pragma unroll
                for (int j = 0; j < 4; j++)
                    acc[i][j] += a[i] * bb[j];
        }
        __syncthreads();
    }
    #pragma unroll
    for (int i = 0; i < 4; i++) {
        int gm = m0 + ty * 4 + i;
        float sm = sb[gm];
        #pragma unroll
        for (int j = 0; j < 4; j++) {
            int gn = n0 + tx * 4 + j;
            D[(size_t)gm * NPTS + gn] = sm + sb[gn] - 2.f * acc[i][j];
        }
    }
}

// ---------------- sq[row] = sum_d key[row,d]^2 (warp per row) ----------------
__global__ void sq_kernel(const float* __restrict__ key, float* __restrict__ sq)
{
    int w = (blockIdx.x * blockDim.x + threadIdx.x) >> 5;
    int lane = threadIdx.x & 31;
    if (w < M1) {
        const float* p = key + (size_t)w * C_;
        float s = 0.f;
        for (int d = lane; d < C_; d += 32) { float v = p[d]; s += v * v; }
        #pragma unroll
        for (int o = 16; o; o >>= 1) s += __shfl_down_sync(0xffffffffu, s, o);
        if (lane == 0) sq[w] = s;
    }
}

// ---------------- top-32 smallest per row, tie-break smaller index ----------------
__global__ __launch_bounds__(256)
void topk_kernel(const float* __restrict__ dist)
{
    int bn = blockIdx.x;
    const float* row = dist + (size_t)bn * NPTS;
    __shared__ float sv[NPTS];
    __shared__ float rv[256];
    __shared__ int   ri[256];
    int t = threadIdx.x;
    for (int j = t; j < NPTS; j += 256) sv[j] = row[j];
    __syncthreads();

    for (int sel = 0; sel < KNB; sel++) {
        float best = FLT_MAX; int bi = 1 << 30;
        for (int j = t; j < NPTS; j += 256) {
            float v = sv[j];
            if (v < best || (v == best && j < bi)) { best = v; bi = j; }
        }
        rv[t] = best; ri[t] = bi;
        __syncthreads();
        for (int s = 128; s > 0; s >>= 1) {
            if (t < s) {
                if (rv[t + s] < rv[t] || (rv[t + s] == rv[t] && ri[t + s] < ri[t])) {
                    rv[t] = rv[t + s]; ri[t] = ri[t + s];
                }
            }
            __syncthreads();
        }
        if (t == 0) {
            g_idx[(size_t)bn * KNB + sel] = ri[0];
            sv[ri[0]] = FLT_MAX;
        }
        __syncthreads();
    }
}

// ---------------- per-channel batch stats ----------------
__global__ void zero_stats_kernel(int D)
{
    int i = blockIdx.x * blockDim.x + threadIdx.x;
    if (i < D) { g_dsum[i] = 0.0; g_dsum2[i] = 0.0; }
}

__global__ void stats_partial_kernel(const float* __restrict__ Y, int M, int D)
{
    int d = blockIdx.x * 32 + threadIdx.x;
    int stride = gridDim.y * blockDim.y;
    float s = 0.f, s2 = 0.f;
    if (d < D) {
        for (int i = blockIdx.y * blockDim.y + threadIdx.y; i < M; i += stride) {
            float v = Y[(size_t)i * D + d];
            s += v; s2 += v * v;
        }
    }
    __shared__ float sh[8][32], sh2[8][32];
    sh[threadIdx.y][threadIdx.x]  = s;
    sh2[threadIdx.y][threadIdx.x] = s2;
    __syncthreads();
    if (threadIdx.y == 0 && d < D) {
        double ts = 0.0, ts2 = 0.0;
        #pragma unroll
        for (int r = 0; r < 8; r++) { ts += sh[r][threadIdx.x]; ts2 += sh2[r][threadIdx.x]; }
        atomicAdd(&g_dsum[d], ts);
        atomicAdd(&g_dsum2[d], ts2);
    }
}

__global__ void stats_finalize_kernel(int M, int D)
{
    int d = blockIdx.x * blockDim.x + threadIdx.x;
    if (d < D) {
        double m = g_dsum[d] / (double)M;
        double v = g_dsum2[d] / (double)M - m * m;
        g_mean[d] = (float)m;
        g_var[d]  = (float)(v < 0.0 ? 0.0 : v);
    }
}

// ---------------- BN + activations ----------------
__global__ void bn_leaky_kernel(const float* __restrict__ Y, const float* __restrict__ gamma,
                                const float* __restrict__ beta, float* __restrict__ out,
                                int D, size_t total)
{
    size_t e = (size_t)blockIdx.x * blockDim.x + threadIdx.x;
    if (e < total) {
        int d = (int)(e % D);
        float z = (Y[e] - g_mean[d]) * rsqrtf(g_var[d] + EPSB) * gamma[d] + beta[d];
        out[e] = z >= 0.f ? z : 0.2f * z;
    }
}

__global__ void bn_silu_kernel(const float* __restrict__ Y, const float* __restrict__ gamma,
                               const float* __restrict__ beta, float* __restrict__ out,
                               int D, size_t total)
{
    size_t e = (size_t)blockIdx.x * blockDim.x + threadIdx.x;
    if (e < total) {
        int d = (int)(e % D);
        float z = (Y[e] - g_mean[d]) * rsqrtf(g_var[d] + EPSB) * gamma[d] + beta[d];
        out[e] = z / (1.f + expf(-z));
    }
}

__global__ void bn_silu_res_kernel(const float* __restrict__ Y, const float* __restrict__ gamma,
                                   const float* __restrict__ beta, const float* __restrict__ res,
                                   float* __restrict__ out, int D, size_t total)
{
    size_t e = (size_t)blockIdx.x * blockDim.x + threadIdx.x;
    if (e < total) {
        int d = (int)(e % D);
        float z = (Y[e] - g_mean[d]) * rsqrtf(g_var[d] + EPSB) * gamma[d] + beta[d];
        out[e] = res[e] + z / (1.f + expf(-z));
    }
}

// ---------------- masked_pos gather ----------------
__global__ void mpos_kernel(const float* __restrict__ pos)
{
    size_t e = (size_t)blockIdx.x * blockDim.x + threadIdx.x;
    const size_t total = (size_t)M2 * C_;
    if (e < total) {
        int d = (int)(e & (C_ - 1));
        size_t m = e >> 8;              // (b*N+n)*K + k
        int bn = (int)(m >> 5);         // b*N+n
        int b  = bn >> 11;              // /2048
        int j  = g_idx[m];
        g_big0[e] = pos[((size_t)(b * NPTS + j)) * C_ + d] - pos[(size_t)bn * C_ + d];
    }
}

// ---------------- posb BN/leaky + value/vecin combine ----------------
__global__ void posb_combine_kernel(const float* __restrict__ gpb, const float* __restrict__ bpb)
{
    size_t e = (size_t)blockIdx.x * blockDim.x + threadIdx.x;
    const size_t total = (size_t)M2 * C_;
    if (e < total) {
        int d = (int)(e & (C_ - 1));
        size_t m = e >> 8;
        int bn = (int)(m >> 5);
        int b  = bn >> 11;
        int j  = g_idx[m];
        size_t nb = ((size_t)(b * NPTS + j)) * C_ + d;
        float p = (g_big1[e] - g_mean[d]) * rsqrtf(g_var[d] + EPSB) * gpb[d] + bpb[d];
        p = p >= 0.f ? p : 0.2f * p;
        g_big2[e] = g_v[nb] + p;                                   // value
        g_big0[e] = g_k[nb] - g_q[(size_t)bn * C_ + d] + p;        // vecin (reuse)
    }
}

// ---------------- softmax over k + attention + residual ----------------
__global__ __launch_bounds__(256)
void attn_kernel(const float* __restrict__ x, float* __restrict__ xattn)
{
    int bn = blockIdx.x;
    int t = threadIdx.x;
    __shared__ float sv[KNB][CPH];
    __shared__ float soft[KNB][CPH];
    size_t base = (size_t)bn * KNB * CPH;
    for (int e = t; e < KNB * CPH; e += 256)
        sv[e >> 5][e & 31] = g_s2[base + e];
    __syncthreads();
    if (t < CPH) {
        int g = t;
        float mx = -FLT_MAX;
        #pragma unroll
        for (int k = 0; k < KNB; k++) mx = fmaxf(mx, sv[k][g]);
        float s = 0.f;
        #pragma unroll
        for (int k = 0; k < KNB; k++) { float ev = expf(sv[k][g] - mx); soft[k][g] = ev; s += ev; }
        float inv = 1.f / s;
        #pragma unroll
        for (int k = 0; k < KNB; k++) soft[k][g] *= inv;
    }
    __syncthreads();
    // t = output channel c in [0,256)
    int g = t >> 3;
    const float* vrow = g_big2 + (size_t)bn * KNB * C_;
    float acc = 0.f;
    #pragma unroll
    for (int k = 0; k < KNB; k++) acc += vrow[(size_t)k * C_ + t] * soft[k][g];
    size_t o = (size_t)bn * C_ + t;
    xattn[o] = x[o] + acc;
}

// ---------------- host-side helpers ----------------
static inline void run_stats(const float* Y, int M, int D, int splits)
{
    zero_stats_kernel<<<(D + 255) / 256, 256>>>(D);
    dim3 grid((D + 31) / 32, splits);
    dim3 blk(32, 8);
    stats_partial_kernel<<<grid, blk>>>(Y, M, D);
    stats_finalize_kernel<<<(D + 255) / 256, 256>>>(M, D);
}

static inline void run_gemm(const float* A, const float* W, float* C, int M, int N, int K)
{
    dim3 grid((N + 63) / 64, (M + 63) / 64);
    gemm_tn_kernel<<<grid, 256>>>(A, W, C, M, N, K);
}

extern "C" void kernel_launch(void* const* d_in, const int* in_sizes, int n_in,
                              void* d_out, int out_size)
{
    const float* x   = (const float*)d_in[0];
    const float* pos = (const float*)d_in[1];
    const float* Wq  = (const float*)d_in[2];
    const float* gq  = (const float*)d_in[3];
    const float* bq  = (const float*)d_in[4];
    const float* Wk  = (const float*)d_in[5];
    const float* gk  = (const float*)d_in[6];
    const float* bk  = (const float*)d_in[7];
    const float* Wv  = (const float*)d_in[8];
    const float* gv  = (const float*)d_in[9];
    const float* bv  = (const float*)d_in[10];
    const float* Wpb = (const float*)d_in[11];
    const float* gpb = (const float*)d_in[12];
    const float* bpb = (const float*)d_in[13];
    const float* We1 = (const float*)d_in[14];
    const float* ge1 = (const float*)d_in[15];
    const float* be1 = (const float*)d_in[16];
    const float* We2 = (const float*)d_in[17];
    const float* ge2 = (const float*)d_in[18];
    const float* be2 = (const float*)d_in[19];
    const float* Wm1 = (const float*)d_in[20];
    const float* gm1 = (const float*)d_in[21];
    const float* bm1 = (const float*)d_in[22];
    const float* Wm2 = (const float*)d_in[23];
    const float* gm2 = (const float*)d_in[24];
    const float* bm2 = (const float*)d_in[25];
    float* out = (float*)d_out;

    void* p;
    float *q, *k, *v, *tmp, *sqb, *dist, *big0, *big1, *s1, *s2, *xatt, *hbuf;
    cudaGetSymbolAddress(&p, g_q);     q    = (float*)p;
    cudaGetSymbolAddress(&p, g_k);     k    = (float*)p;
    cudaGetSymbolAddress(&p, g_v);     v    = (float*)p;
    cudaGetSymbolAddress(&p, g_tmp);   tmp  = (float*)p;
    cudaGetSymbolAddress(&p, g_sq);    sqb  = (float*)p;
    cudaGetSymbolAddress(&p, g_dist);  dist = (float*)p;
    cudaGetSymbolAddress(&p, g_big0);  big0 = (float*)p;
    cudaGetSymbolAddress(&p, g_big1);  big1 = (float*)p;
    cudaGetSymbolAddress(&p, g_s1);    s1   = (float*)p;
    cudaGetSymbolAddress(&p, g_s2);    s2   = (float*)p;
    cudaGetSymbolAddress(&p, g_xattn); xatt = (float*)p;
    cudaGetSymbolAddress(&p, g_h);     hbuf = (float*)p;

    const size_t tot1  = (size_t)M1 * C_;
    const size_t totB  = (size_t)M2 * C_;
    const size_t totS  = (size_t)M2 * CPH;
    const int BLK = 256;

    // ---- q, key, val = conv1(x, W*, g*, b*) ----
    run_gemm(x, Wq, tmp, M1, C_, C_);
    run_stats(tmp, M1, C_, 16);
    bn_leaky_kernel<<<(int)((tot1 + BLK - 1) / BLK), BLK>>>(tmp, gq, bq, q, C_, tot1);

    run_gemm(x, Wk, tmp, M1, C_, C_);
    run_stats(tmp, M1, C_, 16);
    bn_leaky_kernel<<<(int)((tot1 + BLK - 1) / BLK), BLK>>>(tmp, gk, bk, k, C_, tot1);

    run_gemm(x, Wv, tmp, M1, C_, C_);
    run_stats(tmp, M1, C_, 16);
    bn_leaky_kernel<<<(int)((tot1 + BLK - 1) / BLK), BLK>>>(tmp, gv, bv, v, C_, tot1);

    // ---- kNN: sq, dist, topk ----
    sq_kernel<<<(M1 * 32 + BLK - 1) / BLK, BLK>>>(k, sqb);
    {
        dim3 grid(NPTS / 64, NPTS / 64, B_);
        dist_kernel<<<grid, 256>>>(k, sqb, dist);
    }
    topk_kernel<<<M1, 256>>>(dist);

    // ---- masked_pos gather + posb conv2 ----
    mpos_kernel<<<(int)((totB + BLK - 1) / BLK), BLK>>>(pos);
    run_gemm(big0, Wpb, big1, M2, C_, C_);
    run_stats(big1, M2, C_, 64);
    posb_combine_kernel<<<(int)((totB + BLK - 1) / BLK), BLK>>>(gpb, bpb);

    // ---- vector = conv2(conv2(vecin, We1), We2) ----
    run_gemm(big0, We1, s1, M2, CPH, C_);
    run_stats(s1, M2, CPH, 64);
    bn_leaky_kernel<<<(int)((totS + BLK - 1) / BLK), BLK>>>(s1, ge1, be1, s1, CPH, totS);

    run_gemm(s1, We2, s2, M2, CPH, CPH);
    run_stats(s2, M2, CPH, 64);
    bn_leaky_kernel<<<(int)((totS + BLK - 1) / BLK), BLK>>>(s2, ge2, be2, s2, CPH, totS);

    // ---- softmax over k, attention, residual ----
    attn_kernel<<<M1, 256>>>(x, xatt);

    // ---- MLP: h = silu(bn(xattn @ Wm1^T)); m = silu(bn(h @ Wm2^T)); out = xattn + m ----
    run_gemm(xatt, Wm1, tmp, M1, HID, C_);
    run_stats(tmp, M1, HID, 16);
    {
        size_t t2 = (size_t)M1 * HID;
        bn_silu_kernel<<<(int)((t2 + BLK - 1) / BLK), BLK>>>(tmp, gm1, bm1, hbuf, HID, t2);
    }

    run_gemm(hbuf, Wm2, tmp, M1, C_, HID);
    run_stats(tmp, M1, C_, 16);
    bn_silu_res_kernel<<<(int)((tot1 + BLK - 1) / BLK), BLK>>>(tmp, gm2, bm2, xatt, out, C_, tot1);
}